// round 15
// baseline (speedup 1.0000x reference)
#include <cuda_runtime.h>

// AbstractRelu (DeepPoly ReLU relaxation), elementwise over N fp32.
// out layout: [relu(x) (N)] [lb_slope*low (N)] [relu(high) (N)]
//
// CONVERGED FINAL (R5; verified stable across R8/R10-R14; best observed
// 63.10us wall / 55.3us kernel, DRAM 79.5%, HBM 6299 GB/s; run-to-run band
// 63.1-63.6us for the byte-identical binary). Search history (15 benches):
//   R1  256t float4 sequential ................ 63.7
//   R2  2-quad FRONT-BATCHED loads ............ 65.6  (L1tex queue contention)
//   R3  R1 + .cs hints ........................ 63.6  (hints neutral)
//   R4  persistent grid 1184 CTAs ............. 71.7  (regressed)
//   R5  128t float4 sequential + .cs .......... 63.3  << best config
//   R6  2-quad sequential (fenced) ............ 63.8  (neutral)
//   R7  256-bit v8.f32 ld/st .................. 64.2  (issue not binding)
//   R8-R14 reproductions ...................... 63.1-63.6 (noise band)
// Traffic is at the 402MB floor (3 fp32 reads + 3 fp32 writes, zero reuse,
// output layout fixed by harness); ~7.3 TB/s kernel-visible = B300 LTS cap.
// Residual DRAM-pipe headroom is HBM R/W bus turnaround -- not addressable
// from SASS. No remaining lever for this workload.

__global__ void __launch_bounds__(128, 16)
abstract_relu_kernel(const float4* __restrict__ x,
                     const float4* __restrict__ low,
                     const float4* __restrict__ high,
                     float4* __restrict__ x_out,
                     float4* __restrict__ low_out,
                     float4* __restrict__ high_out,
                     int n4)
{
    int i = blockIdx.x * blockDim.x + threadIdx.x;
    if (i >= n4) return;

    float4 xv = __ldcs(&x[i]);
    float4 lv = __ldcs(&low[i]);
    float4 hv = __ldcs(&high[i]);

    float4 xo, lo, ho;

    #define LANE(f)                                                        \
    {                                                                      \
        float xe = xv.f, le = lv.f, he = hv.f;                             \
        xo.f = fmaxf(xe, 0.0f);                                            \
        ho.f = fmaxf(he, 0.0f);                                            \
        bool zero = (he <= 0.0f) || (le < 0.0f && le * le > he * he);      \
        lo.f = zero ? 0.0f : le;                                           \
    }

    LANE(x) LANE(y) LANE(z) LANE(w)
    #undef LANE

    __stcs(&x_out[i],    xo);
    __stcs(&low_out[i],  lo);
    __stcs(&high_out[i], ho);
}

extern "C" void kernel_launch(void* const* d_in, const int* in_sizes, int n_in,
                              void* d_out, int out_size)
{
    const float* x    = (const float*)d_in[0];
    const float* low  = (const float*)d_in[1];
    const float* high = (const float*)d_in[2];
    float* out = (float*)d_out;

    const int n  = in_sizes[0];          // 16777216
    const int n4 = n / 4;                // 4194304

    float* x_out    = out;
    float* low_out  = out + n;
    float* high_out = out + 2 * (size_t)n;

    const int threads = 128;
    const int blocks  = (n4 + threads - 1) / threads;  // 32768

    abstract_relu_kernel<<<blocks, threads>>>(
        (const float4*)x, (const float4*)low, (const float4*)high,
        (float4*)x_out, (float4*)low_out, (float4*)high_out, n4);
}

// round 16
// speedup vs baseline: 1.0046x; 1.0046x over previous
#include <cuda_runtime.h>

// AbstractRelu (DeepPoly ReLU relaxation), elementwise over N fp32.
// out layout: [relu(x) (N)] [lb_slope*low (N)] [relu(high) (N)]
//
// CONVERGED FINAL (R5; verified byte-identical-stable across R8/R10-R15;
// best observed 63.10us wall / 55.3us kernel; run-to-run band 63.1-63.6us).
// Search history (16 benches):
//   R1  256t float4 sequential ................ 63.7
//   R2  2-quad FRONT-BATCHED loads ............ 65.6  (L1tex queue contention)
//   R3  R1 + .cs hints ........................ 63.6  (hints neutral)
//   R4  persistent grid 1184 CTAs ............. 71.7  (regressed)
//   R5  128t float4 sequential + .cs .......... 63.3  << best config
//   R6  2-quad sequential (fenced) ............ 63.8  (neutral)
//   R7  256-bit v8.f32 ld/st .................. 64.2  (issue not binding)
//   R8-R15 reproductions ...................... 63.1-63.6 (noise band)
// Traffic at the 402MB floor; ~7.2-7.3 TB/s kernel-visible = B300 LTS cap
// (~90% of 8TB/s spec). Residual DRAM-pipe headroom is HBM R/W bus
// turnaround -- not addressable from SASS. Workload is closed.

__global__ void __launch_bounds__(128, 16)
abstract_relu_kernel(const float4* __restrict__ x,
                     const float4* __restrict__ low,
                     const float4* __restrict__ high,
                     float4* __restrict__ x_out,
                     float4* __restrict__ low_out,
                     float4* __restrict__ high_out,
                     int n4)
{
    int i = blockIdx.x * blockDim.x + threadIdx.x;
    if (i >= n4) return;

    float4 xv = __ldcs(&x[i]);
    float4 lv = __ldcs(&low[i]);
    float4 hv = __ldcs(&high[i]);

    float4 xo, lo, ho;

    #define LANE(f)                                                        \
    {                                                                      \
        float xe = xv.f, le = lv.f, he = hv.f;                             \
        xo.f = fmaxf(xe, 0.0f);                                            \
        ho.f = fmaxf(he, 0.0f);                                            \
        bool zero = (he <= 0.0f) || (le < 0.0f && le * le > he * he);      \
        lo.f = zero ? 0.0f : le;                                           \
    }

    LANE(x) LANE(y) LANE(z) LANE(w)
    #undef LANE

    __stcs(&x_out[i],    xo);
    __stcs(&low_out[i],  lo);
    __stcs(&high_out[i], ho);
}

extern "C" void kernel_launch(void* const* d_in, const int* in_sizes, int n_in,
                              void* d_out, int out_size)
{
    const float* x    = (const float*)d_in[0];
    const float* low  = (const float*)d_in[1];
    const float* high = (const float*)d_in[2];
    float* out = (float*)d_out;

    const int n  = in_sizes[0];          // 16777216
    const int n4 = n / 4;                // 4194304

    float* x_out    = out;
    float* low_out  = out + n;
    float* high_out = out + 2 * (size_t)n;

    const int threads = 128;
    const int blocks  = (n4 + threads - 1) / threads;  // 32768

    abstract_relu_kernel<<<blocks, threads>>>(
        (const float4*)x, (const float4*)low, (const float4*)high,
        (float4*)x_out, (float4*)low_out, (float4*)high_out, n4);
}